// round 2
// baseline (speedup 1.0000x reference)
#include <cuda_runtime.h>
#include <cstdint>

#define NBLOCKS 1024
#define NTHREADS 256

// Block partial sums — device-global scratch (no allocations allowed).
__device__ float g_partials[NBLOCKS];

// Stable BCE-with-logits: max(x,0) - x*z + log1p(exp(-|x|))
// Fast-math variant: intrinsic exp/log keep MUFU cost at 2 ops/elem so the
// kernel stays HBM-bound.
__device__ __forceinline__ float bce_term(float x, float z) {
    float a = fabsf(x);
    float soft = __logf(1.0f + __expf(-a));          // log1p(exp(-|x|)), |x|>=0 so arg in (1,2]
    return fmaxf(x, 0.0f) - x * z + soft;
}

__global__ void __launch_bounds__(NTHREADS)
coral_loss_main(const float4* __restrict__ logits4,
                const long long* __restrict__ targets,
                int n_vec)   // n_vec = B * 16  (16 float4 per row of 64)
{
    float acc = 0.0f;
    const int stride = gridDim.x * blockDim.x;
    for (int i = blockIdx.x * blockDim.x + threadIdx.x; i < n_vec; i += stride) {
        float4 x = logits4[i];
        int row = i >> 4;                 // 16 float4 per row
        int kbase = (i & 15) << 2;        // starting threshold index for this float4
        long long t = __ldg(&targets[row]);

        float z0 = (t > (long long)(kbase + 0)) ? 1.0f : 0.0f;
        float z1 = (t > (long long)(kbase + 1)) ? 1.0f : 0.0f;
        float z2 = (t > (long long)(kbase + 2)) ? 1.0f : 0.0f;
        float z3 = (t > (long long)(kbase + 3)) ? 1.0f : 0.0f;

        acc += bce_term(x.x, z0);
        acc += bce_term(x.y, z1);
        acc += bce_term(x.z, z2);
        acc += bce_term(x.w, z3);
    }

    // Warp tree reduce (deterministic order)
    #pragma unroll
    for (int off = 16; off > 0; off >>= 1)
        acc += __shfl_xor_sync(0xffffffffu, acc, off);

    __shared__ float smem[NTHREADS / 32];
    if ((threadIdx.x & 31) == 0)
        smem[threadIdx.x >> 5] = acc;
    __syncthreads();

    if (threadIdx.x < 32) {
        float v = (threadIdx.x < (NTHREADS / 32)) ? smem[threadIdx.x] : 0.0f;
        #pragma unroll
        for (int off = 4; off > 0; off >>= 1)
            v += __shfl_xor_sync(0xffffffffu, v, off);
        if (threadIdx.x == 0)
            g_partials[blockIdx.x] = v;
    }
}

__global__ void __launch_bounds__(NTHREADS)
coral_loss_final(float* __restrict__ out, float inv_n)
{
    // Single block: each thread sums a strided slice of the partials
    // (fixed order -> deterministic), then tree-reduce.
    float acc = 0.0f;
    for (int i = threadIdx.x; i < NBLOCKS; i += NTHREADS)
        acc += g_partials[i];

    #pragma unroll
    for (int off = 16; off > 0; off >>= 1)
        acc += __shfl_xor_sync(0xffffffffu, acc, off);

    __shared__ float smem[NTHREADS / 32];
    if ((threadIdx.x & 31) == 0)
        smem[threadIdx.x >> 5] = acc;
    __syncthreads();

    if (threadIdx.x < 32) {
        float v = (threadIdx.x < (NTHREADS / 32)) ? smem[threadIdx.x] : 0.0f;
        #pragma unroll
        for (int off = 4; off > 0; off >>= 1)
            v += __shfl_xor_sync(0xffffffffu, v, off);
        if (threadIdx.x == 0)
            out[0] = v * inv_n;
    }
}

extern "C" void kernel_launch(void* const* d_in, const int* in_sizes, int n_in,
                              void* d_out, int out_size)
{
    const float4* logits4      = (const float4*)d_in[0];
    const long long* targets   = (const long long*)d_in[1];
    float* out                 = (float*)d_out;

    int n_elems = in_sizes[0];            // B * 64
    int n_vec   = n_elems >> 2;           // number of float4

    int blocks = NBLOCKS;
    // Guard for tiny inputs (not expected here, but keep it correct).
    int max_needed = (n_vec + NTHREADS - 1) / NTHREADS;
    if (blocks > max_needed && max_needed > 0) {
        // Zero unused partials so the final reduce stays correct.
        // (Launch full NBLOCKS anyway: blocks beyond the data write 0 partials.)
    }

    coral_loss_main<<<blocks, NTHREADS>>>(logits4, targets, n_vec);
    coral_loss_final<<<1, NTHREADS>>>(out, 1.0f / (float)n_elems);
}

// round 3
// speedup vs baseline: 1.0650x; 1.0650x over previous
#include <cuda_runtime.h>
#include <cstdint>

#define NBLOCKS 1024
#define NTHREADS 256

// Device-global scratch (no allocations allowed).
__device__ float g_partials[NBLOCKS];
__device__ unsigned int g_count = 0;

__global__ void __launch_bounds__(NTHREADS)
coral_loss_fused(const float4* __restrict__ logits4,
                 const int* __restrict__ targets_lo,  // low 32 bits of int64 targets
                 float* __restrict__ out,
                 int n_vec,        // number of float4 = B*16
                 float inv_n)      // 1 / (B * (K-1))
{
    float acc  = 0.0f;   // relu + (-x when z=1) terms
    float accL = 0.0f;   // summed log terms
    const int stride = gridDim.x * blockDim.x;
    const int tid0 = blockIdx.x * blockDim.x + threadIdx.x;

    // Grid-stride, 4 float4 (=16 elements) per outer iteration; one LG2 per 16.
    for (int i = tid0; i < n_vec; i += 4 * stride) {
        float p = 1.0f;   // product of (1 + exp(-|x|)) over up to 16 elements
        #pragma unroll
        for (int u = 0; u < 4; u++) {
            int j = i + u * stride;
            if (j < n_vec) {
                float4 x = logits4[j];
                int row   = j >> 4;            // 16 float4 per row of 64
                int kbase = (j & 15) << 2;     // threshold index of x.x
                int t = __ldg(&targets_lo[(size_t)row << 1]);   // int64 low word

                // max(x,0) - x*z  ==  relu(x) - (z ? x : 0)
                acc += fmaxf(x.x, 0.0f);  if (t > kbase)     acc -= x.x;
                acc += fmaxf(x.y, 0.0f);  if (t > kbase + 1) acc -= x.y;
                acc += fmaxf(x.z, 0.0f);  if (t > kbase + 2) acc -= x.z;
                acc += fmaxf(x.w, 0.0f);  if (t > kbase + 3) acc -= x.w;

                // p *= (1 + exp(-|x_i|))  — single FFMA each
                float e0 = __expf(-fabsf(x.x));
                float e1 = __expf(-fabsf(x.y));
                float e2 = __expf(-fabsf(x.z));
                float e3 = __expf(-fabsf(x.w));
                p = __fmaf_rn(p, e0, p);
                p = __fmaf_rn(p, e1, p);
                p = __fmaf_rn(p, e2, p);
                p = __fmaf_rn(p, e3, p);
            }
        }
        accL += __logf(p);   // p in [1, 2^16] — exact-safe in fp32
    }
    acc += accL;

    // Warp tree reduce (deterministic)
    #pragma unroll
    for (int off = 16; off > 0; off >>= 1)
        acc += __shfl_xor_sync(0xffffffffu, acc, off);

    __shared__ float smem[NTHREADS / 32];
    if ((threadIdx.x & 31) == 0)
        smem[threadIdx.x >> 5] = acc;
    __syncthreads();

    if (threadIdx.x < 32) {
        float v = (threadIdx.x < (NTHREADS / 32)) ? smem[threadIdx.x] : 0.0f;
        #pragma unroll
        for (int off = 4; off > 0; off >>= 1)
            v += __shfl_xor_sync(0xffffffffu, v, off);
        if (threadIdx.x == 0)
            g_partials[blockIdx.x] = v;
    }
    __syncthreads();

    // Last-block-done final reduction (fused; kills the second kernel launch).
    __shared__ unsigned int s_is_last;
    if (threadIdx.x == 0) {
        __threadfence();
        unsigned int prev = atomicAdd(&g_count, 1u);
        s_is_last = (prev == gridDim.x - 1) ? 1u : 0u;
    }
    __syncthreads();

    if (s_is_last) {
        // Fixed-order strided sum over all block partials -> deterministic.
        float a = 0.0f;
        for (int i = threadIdx.x; i < (int)gridDim.x; i += NTHREADS)
            a += g_partials[i];

        #pragma unroll
        for (int off = 16; off > 0; off >>= 1)
            a += __shfl_xor_sync(0xffffffffu, a, off);

        if ((threadIdx.x & 31) == 0)
            smem[threadIdx.x >> 5] = a;
        __syncthreads();

        if (threadIdx.x < 32) {
            float v = (threadIdx.x < (NTHREADS / 32)) ? smem[threadIdx.x] : 0.0f;
            #pragma unroll
            for (int off = 4; off > 0; off >>= 1)
                v += __shfl_xor_sync(0xffffffffu, v, off);
            if (threadIdx.x == 0) {
                out[0] = v * inv_n;
                g_count = 0;          // reset for next graph replay
            }
        }
    }
}

extern "C" void kernel_launch(void* const* d_in, const int* in_sizes, int n_in,
                              void* d_out, int out_size)
{
    const float4* logits4  = (const float4*)d_in[0];
    const int* targets_lo  = (const int*)d_in[1];   // int64 targets, read low words
    float* out             = (float*)d_out;

    int n_elems = in_sizes[0];            // B * 64
    int n_vec   = n_elems >> 2;           // number of float4

    coral_loss_fused<<<NBLOCKS, NTHREADS>>>(logits4, targets_lo, out,
                                            n_vec, 1.0f / (float)n_elems);
}